// round 7
// baseline (speedup 1.0000x reference)
#include <cuda_runtime.h>
#include <cuda_bf16.h>

#define B_      4
#define CIN     256
#define HH      32
#define WW      88
#define HW      2816
#define PTOT    11264
#define COUT    128
#define OUTH    432
#define OUTW    496
#define XVEC    124             // 496/4
#define NPLANE  512
#define YTILE   54              // 432 = 8*54
#define NYT     8
#define SROWS   6
#define YHALF   27

#define KC      32              // GEMM k-chunk
#define PB      64              // positions per block
#define CB      64              // channels per block

__device__ float g_ctx[NPLANE * HW];
__device__ float g_WcT[CIN * COUT];   // [k][c], pre-scaled by 1/64

// ---------------------------------------------------------------------------
// Kernel 0: transpose + scale weight slice: WcT[k][c] = Wc[64+c][k] / 64
// ---------------------------------------------------------------------------
__global__ __launch_bounds__(256)
void lss_prep_kernel(const float* __restrict__ Wc)
{
    int i = blockIdx.x * 256 + threadIdx.x;   // 32768 total
    int k = i >> 7, c = i & 127;
    g_WcT[i] = Wc[(64 + c) * CIN + k] * (1.0f / 64.0f);
}

// ---------------------------------------------------------------------------
// Kernel 1: GEMM (R4 proven version). Block 64c x 64p, 128 threads,
// thread tile 8c x 4p, double-buffered KC=32.
// ---------------------------------------------------------------------------
__global__ __launch_bounds__(128)
void lss_gemm_kernel(const float* __restrict__ feat,
                     const float* __restrict__ bc)
{
    __shared__ float Ws[2][KC * CB];   // 16KB
    __shared__ float Fs[2][KC * PB];   // 16KB

    const int tid   = threadIdx.x;
    const int p0    = blockIdx.x * PB;
    const int b     = p0 / HW;
    const int hw0   = p0 - b * HW;
    const int cbase = blockIdx.y * CB;          // 0 or 64

    const float4* WcT4  = (const float4*)g_WcT;
    const float4* feat4 = (const float4*)(feat + (size_t)b * CIN * HW + hw0);

    const int lkk = tid >> 4;        // 0..7
    const int lcv = tid & 15;        // 0..15

    float4 wreg[4], freg[4];

#pragma unroll
    for (int it = 0; it < 4; it++) {
        int kk = lkk + it * 8;
        wreg[it] = WcT4[(size_t)kk * 32 + (cbase >> 2) + lcv];
        freg[it] = feat4[(size_t)kk * 704 + lcv];
    }
#pragma unroll
    for (int it = 0; it < 4; it++) {
        int kk = lkk + it * 8;
        ((float4*)Ws[0])[kk * 16 + lcv] = wreg[it];
        ((float4*)Fs[0])[kk * 16 + lcv] = freg[it];
    }
    __syncthreads();

    const int cy = (tid >> 4) << 3;   // 0..56
    const int px = (tid & 15) << 2;   // 0..60

    float acc[8][4];
#pragma unroll
    for (int i = 0; i < 8; i++)
#pragma unroll
        for (int j = 0; j < 4; j++) acc[i][j] = 0.0f;

    int buf = 0;
    for (int ch = 0; ch < CIN / KC; ch++) {
        if (ch < CIN / KC - 1) {
            int k0 = (ch + 1) * KC;
#pragma unroll
            for (int it = 0; it < 4; it++) {
                int kk = k0 + lkk + it * 8;
                wreg[it] = WcT4[(size_t)kk * 32 + (cbase >> 2) + lcv];
                freg[it] = feat4[(size_t)kk * 704 + lcv];
            }
        }

        const float* Wsb = Ws[buf];
        const float* Fsb = Fs[buf];
#pragma unroll 16
        for (int k = 0; k < KC; k++) {
            float4 w0 = *(const float4*)&Wsb[k * CB + cy];
            float4 w1 = *(const float4*)&Wsb[k * CB + cy + 4];
            float4 f  = *(const float4*)&Fsb[k * PB + px];
            acc[0][0] = fmaf(w0.x, f.x, acc[0][0]); acc[0][1] = fmaf(w0.x, f.y, acc[0][1]);
            acc[0][2] = fmaf(w0.x, f.z, acc[0][2]); acc[0][3] = fmaf(w0.x, f.w, acc[0][3]);
            acc[1][0] = fmaf(w0.y, f.x, acc[1][0]); acc[1][1] = fmaf(w0.y, f.y, acc[1][1]);
            acc[1][2] = fmaf(w0.y, f.z, acc[1][2]); acc[1][3] = fmaf(w0.y, f.w, acc[1][3]);
            acc[2][0] = fmaf(w0.z, f.x, acc[2][0]); acc[2][1] = fmaf(w0.z, f.y, acc[2][1]);
            acc[2][2] = fmaf(w0.z, f.z, acc[2][2]); acc[2][3] = fmaf(w0.z, f.w, acc[2][3]);
            acc[3][0] = fmaf(w0.w, f.x, acc[3][0]); acc[3][1] = fmaf(w0.w, f.y, acc[3][1]);
            acc[3][2] = fmaf(w0.w, f.z, acc[3][2]); acc[3][3] = fmaf(w0.w, f.w, acc[3][3]);
            acc[4][0] = fmaf(w1.x, f.x, acc[4][0]); acc[4][1] = fmaf(w1.x, f.y, acc[4][1]);
            acc[4][2] = fmaf(w1.x, f.z, acc[4][2]); acc[4][3] = fmaf(w1.x, f.w, acc[4][3]);
            acc[5][0] = fmaf(w1.y, f.x, acc[5][0]); acc[5][1] = fmaf(w1.y, f.y, acc[5][1]);
            acc[5][2] = fmaf(w1.y, f.z, acc[5][2]); acc[5][3] = fmaf(w1.y, f.w, acc[5][3]);
            acc[6][0] = fmaf(w1.z, f.x, acc[6][0]); acc[6][1] = fmaf(w1.z, f.y, acc[6][1]);
            acc[6][2] = fmaf(w1.z, f.z, acc[6][2]); acc[6][3] = fmaf(w1.z, f.w, acc[6][3]);
            acc[7][0] = fmaf(w1.w, f.x, acc[7][0]); acc[7][1] = fmaf(w1.w, f.y, acc[7][1]);
            acc[7][2] = fmaf(w1.w, f.z, acc[7][2]); acc[7][3] = fmaf(w1.w, f.w, acc[7][3]);
        }

        if (ch < CIN / KC - 1) {
            int nb = buf ^ 1;
#pragma unroll
            for (int it = 0; it < 4; it++) {
                int kk = lkk + it * 8;
                ((float4*)Ws[nb])[kk * 16 + lcv] = wreg[it];
                ((float4*)Fs[nb])[kk * 16 + lcv] = freg[it];
            }
            __syncthreads();
            buf = nb;
        }
    }

    const float inv64 = 1.0f / 64.0f;
#pragma unroll
    for (int ci = 0; ci < 8; ci++) {
        int cg = cbase + cy + ci;
        float bias = bc[64 + cg] * inv64;
        float4 v;
        v.x = acc[ci][0] + bias;
        v.y = acc[ci][1] + bias;
        v.z = acc[ci][2] + bias;
        v.w = acc[ci][3] + bias;
        *(float4*)&g_ctx[((size_t)(b * COUT + cg)) * HW + hw0 + px] = v;
    }
}

// ---------------------------------------------------------------------------
// Kernel 2: separable bilinear upsample. 256 threads; phase C splits the
// 54 output rows between two 124-thread halves (2x store parallelism).
// ---------------------------------------------------------------------------
__global__ __launch_bounds__(256)
void lss_upsample_kernel(float* __restrict__ out)
{
    __shared__ float raw[SROWS][WW];
    __shared__ float hrow[SROWS][OUTW];
    __shared__ float ywy[YTILE];
    __shared__ int   yi0s[YTILE];

    const int tid   = threadIdx.x;
    const int t     = blockIdx.x;      // 0..7
    const int plane = blockIdx.y;      // 0..511

    const float SY = 32.0f / 432.0f;
    const float OY = 16.0f / 432.0f - 0.5f;
    const float SX = 88.0f / 496.0f;
    const float OX = 44.0f / 496.0f - 0.5f;

    const int rbase = max(4 * t - 1, 0);

    if (tid < YTILE) {
        int Y = t * YTILE + tid;
        float fy = fminf(fmaxf((float)Y * SY + OY, 0.0f), 31.0f);
        int   y0 = (int)fy;
        ywy[tid]  = fy - (float)y0;
        yi0s[tid] = y0 - rbase;        // 0..4, monotone non-decreasing
    }

    // Phase A: load 6 source rows (edge-clamped)
    const float* cb = g_ctx + (size_t)plane * HW;
    for (int i = tid; i < SROWS * WW; i += 256) {
        int r = i / WW, x = i - r * WW;
        int ry = min(rbase + r, HH - 1);
        raw[r][x] = cb[ry * WW + x];
    }
    __syncthreads();

    // Phase B: horizontal interpolation
    for (int i = tid; i < SROWS * 512; i += 256) {
        int r = i >> 9, X = i & 511;
        if (X < OUTW) {
            float fx = fminf(fmaxf((float)X * SX + OX, 0.0f), 87.0f);
            int   x0 = (int)fx;
            float wx = fx - (float)x0;
            int   x1 = min(x0 + 1, WW - 1);
            float a = raw[r][x0];
            hrow[r][X] = fmaf(wx, raw[r][x1] - a, a);
        }
    }
    __syncthreads();

    // Phase C: vertical pass. Two 124-thread halves each cover 27 rows.
    const int half = tid >> 7;         // 0 or 1
    const int lx   = tid & 127;        // x-column within half
    if (lx < XVEC) {
        const int xo    = lx << 2;
        const int ybeg  = half * YHALF;
        const int yend  = ybeg + YHALF;
        float4* orow = (float4*)out + (size_t)plane * OUTH * XVEC
                       + (size_t)(t * YTILE + ybeg) * XVEC + lx;
        int yy = ybeg;
        const int r0 = yi0s[ybeg];
#pragma unroll
        for (int r = 0; r < 5; r++) {
            if (r >= r0 && yy < yend && yi0s[yy] == r) {
                float4 a = *(const float4*)&hrow[r][xo];
                float4 b = *(const float4*)&hrow[r + 1][xo];
                float4 d;
                d.x = b.x - a.x; d.y = b.y - a.y; d.z = b.z - a.z; d.w = b.w - a.w;
                do {
                    float wy = ywy[yy];
                    float4 o;
                    o.x = fmaf(wy, d.x, a.x);
                    o.y = fmaf(wy, d.y, a.y);
                    o.z = fmaf(wy, d.z, a.z);
                    o.w = fmaf(wy, d.w, a.w);
                    __stcs(orow, o);
                    orow += XVEC;
                    yy++;
                } while (yy < yend && yi0s[yy] == r);
            }
        }
    }
}

extern "C" void kernel_launch(void* const* d_in, const int* in_sizes, int n_in,
                              void* d_out, int out_size)
{
    const float* feat = (const float*)d_in[0];
    const float* Wc   = (const float*)d_in[1];
    const float* bc   = (const float*)d_in[2];
    float* out        = (float*)d_out;

    lss_prep_kernel<<<CIN * COUT / 256, 256>>>(Wc);

    dim3 ggrid(PTOT / PB, 2);
    lss_gemm_kernel<<<ggrid, 128>>>(feat, bc);

    dim3 ugrid(NYT, NPLANE);
    lss_upsample_kernel<<<ugrid, 256>>>(out);
}

// round 8
// speedup vs baseline: 1.0257x; 1.0257x over previous
#include <cuda_runtime.h>
#include <cuda_bf16.h>

#define B_      4
#define CIN     256
#define HH      32
#define WW      88
#define HW      2816
#define PTOT    11264
#define COUT    128
#define OUTH    432
#define OUTW    496
#define XVEC    124             // 496/4
#define NPLANE  512
#define YTILE   54              // 432 = 8*54
#define NYT     8
#define SROWS   6
#define YHALF   27

#define KC      32              // GEMM k-chunk
#define PB      64              // positions per block
#define CB      64              // channels per block

__device__ float g_ctx[NPLANE * HW];
__device__ float g_WcT[CIN * COUT];   // [k][c], pre-scaled by 1/64

// ---------------------------------------------------------------------------
// packed f32x2 helpers
// ---------------------------------------------------------------------------
__device__ __forceinline__ unsigned long long pk2(float x) {
    unsigned long long r;
    asm("mov.b64 %0, {%1, %1};" : "=l"(r) : "f"(x));
    return r;
}
__device__ __forceinline__ void ffma2(unsigned long long& d,
                                      unsigned long long a,
                                      unsigned long long b) {
    asm("fma.rn.f32x2 %0, %1, %2, %0;" : "+l"(d) : "l"(a), "l"(b));
}
__device__ __forceinline__ float2 upk(unsigned long long v) {
    float2 r;
    asm("mov.b64 {%0, %1}, %2;" : "=f"(r.x), "=f"(r.y) : "l"(v));
    return r;
}

// ---------------------------------------------------------------------------
// Kernel 0: transpose + scale weight slice: WcT[k][c] = Wc[64+c][k] / 64
// ---------------------------------------------------------------------------
__global__ __launch_bounds__(256)
void lss_prep_kernel(const float* __restrict__ Wc)
{
    int i = blockIdx.x * 256 + threadIdx.x;   // 32768 total
    int k = i >> 7, c = i & 127;
    g_WcT[i] = Wc[(64 + c) * CIN + k] * (1.0f / 64.0f);
}

// ---------------------------------------------------------------------------
// Kernel 1: GEMM. Identical to R7 (register-staged double buffer) except the
// inner loop uses packed fma.rn.f32x2 on channel pairs.
// Block 64c x 64p, 128 threads, thread tile 4 channel-pairs x 4 positions.
// ---------------------------------------------------------------------------
__global__ __launch_bounds__(128)
void lss_gemm_kernel(const float* __restrict__ feat,
                     const float* __restrict__ bc)
{
    __shared__ float Ws[2][KC * CB];   // 16KB
    __shared__ float Fs[2][KC * PB];   // 16KB

    const int tid   = threadIdx.x;
    const int p0    = blockIdx.x * PB;
    const int b     = p0 / HW;
    const int hw0   = p0 - b * HW;
    const int cbase = blockIdx.y * CB;          // 0 or 64

    const float4* WcT4  = (const float4*)g_WcT;
    const float4* feat4 = (const float4*)(feat + (size_t)b * CIN * HW + hw0);

    const int lkk = tid >> 4;        // 0..7
    const int lcv = tid & 15;        // 0..15

    float4 wreg[4], freg[4];

#pragma unroll
    for (int it = 0; it < 4; it++) {
        int kk = lkk + it * 8;
        wreg[it] = WcT4[(size_t)kk * 32 + (cbase >> 2) + lcv];
        freg[it] = feat4[(size_t)kk * 704 + lcv];
    }
#pragma unroll
    for (int it = 0; it < 4; it++) {
        int kk = lkk + it * 8;
        ((float4*)Ws[0])[kk * 16 + lcv] = wreg[it];
        ((float4*)Fs[0])[kk * 16 + lcv] = freg[it];
    }
    __syncthreads();

    const int cy = (tid >> 4) << 3;   // channel base 0..56 (4 pairs)
    const int px = (tid & 15) << 2;   // position base 0..60

    unsigned long long acc[4][4];     // [cpair][pos]
#pragma unroll
    for (int i = 0; i < 4; i++)
#pragma unroll
        for (int j = 0; j < 4; j++) acc[i][j] = 0ull;

    int buf = 0;
    for (int ch = 0; ch < CIN / KC; ch++) {
        if (ch < CIN / KC - 1) {
            int k0 = (ch + 1) * KC;
#pragma unroll
            for (int it = 0; it < 4; it++) {
                int kk = k0 + lkk + it * 8;
                wreg[it] = WcT4[(size_t)kk * 32 + (cbase >> 2) + lcv];
                freg[it] = feat4[(size_t)kk * 704 + lcv];
            }
        }

        const float* Wsb = Ws[buf] + cy;
        const float* Fsb = Fs[buf] + px;
#pragma unroll 16
        for (int k = 0; k < KC; k++) {
            ulonglong2 w01 = *(const ulonglong2*)(Wsb + k * CB);       // pairs (c0,c1),(c2,c3)
            ulonglong2 w23 = *(const ulonglong2*)(Wsb + k * CB + 4);   // pairs (c4,c5),(c6,c7)
            float4 f = *(const float4*)(Fsb + k * PB);
            unsigned long long f0 = pk2(f.x), f1 = pk2(f.y),
                               f2 = pk2(f.z), f3 = pk2(f.w);
            ffma2(acc[0][0], w01.x, f0); ffma2(acc[0][1], w01.x, f1);
            ffma2(acc[0][2], w01.x, f2); ffma2(acc[0][3], w01.x, f3);
            ffma2(acc[1][0], w01.y, f0); ffma2(acc[1][1], w01.y, f1);
            ffma2(acc[1][2], w01.y, f2); ffma2(acc[1][3], w01.y, f3);
            ffma2(acc[2][0], w23.x, f0); ffma2(acc[2][1], w23.x, f1);
            ffma2(acc[2][2], w23.x, f2); ffma2(acc[2][3], w23.x, f3);
            ffma2(acc[3][0], w23.y, f0); ffma2(acc[3][1], w23.y, f1);
            ffma2(acc[3][2], w23.y, f2); ffma2(acc[3][3], w23.y, f3);
        }

        if (ch < CIN / KC - 1) {
            int nb = buf ^ 1;
#pragma unroll
            for (int it = 0; it < 4; it++) {
                int kk = lkk + it * 8;
                ((float4*)Ws[nb])[kk * 16 + lcv] = wreg[it];
                ((float4*)Fs[nb])[kk * 16 + lcv] = freg[it];
            }
            __syncthreads();
            buf = nb;
        }
    }

    const float inv64 = 1.0f / 64.0f;
#pragma unroll
    for (int j = 0; j < 4; j++) {
        int c0 = cbase + cy + 2 * j;
        float b0 = bc[64 + c0] * inv64;
        float b1 = bc[64 + c0 + 1] * inv64;
        float2 v0 = upk(acc[j][0]), v1 = upk(acc[j][1]),
               v2 = upk(acc[j][2]), v3 = upk(acc[j][3]);
        float4 r0 = make_float4(v0.x + b0, v1.x + b0, v2.x + b0, v3.x + b0);
        float4 r1 = make_float4(v0.y + b1, v1.y + b1, v2.y + b1, v3.y + b1);
        *(float4*)&g_ctx[((size_t)(b * COUT + c0)) * HW + hw0 + px]     = r0;
        *(float4*)&g_ctx[((size_t)(b * COUT + c0 + 1)) * HW + hw0 + px] = r1;
    }
}

// ---------------------------------------------------------------------------
// Kernel 2: separable bilinear upsample (R7 proven version, unchanged).
// ---------------------------------------------------------------------------
__global__ __launch_bounds__(256)
void lss_upsample_kernel(float* __restrict__ out)
{
    __shared__ float raw[SROWS][WW];
    __shared__ float hrow[SROWS][OUTW];
    __shared__ float ywy[YTILE];
    __shared__ int   yi0s[YTILE];

    const int tid   = threadIdx.x;
    const int t     = blockIdx.x;      // 0..7
    const int plane = blockIdx.y;      // 0..511

    const float SY = 32.0f / 432.0f;
    const float OY = 16.0f / 432.0f - 0.5f;
    const float SX = 88.0f / 496.0f;
    const float OX = 44.0f / 496.0f - 0.5f;

    const int rbase = max(4 * t - 1, 0);

    if (tid < YTILE) {
        int Y = t * YTILE + tid;
        float fy = fminf(fmaxf((float)Y * SY + OY, 0.0f), 31.0f);
        int   y0 = (int)fy;
        ywy[tid]  = fy - (float)y0;
        yi0s[tid] = y0 - rbase;        // 0..4, monotone non-decreasing
    }

    // Phase A: load 6 source rows (edge-clamped)
    const float* cb = g_ctx + (size_t)plane * HW;
    for (int i = tid; i < SROWS * WW; i += 256) {
        int r = i / WW, x = i - r * WW;
        int ry = min(rbase + r, HH - 1);
        raw[r][x] = cb[ry * WW + x];
    }
    __syncthreads();

    // Phase B: horizontal interpolation
    for (int i = tid; i < SROWS * 512; i += 256) {
        int r = i >> 9, X = i & 511;
        if (X < OUTW) {
            float fx = fminf(fmaxf((float)X * SX + OX, 0.0f), 87.0f);
            int   x0 = (int)fx;
            float wx = fx - (float)x0;
            int   x1 = min(x0 + 1, WW - 1);
            float a = raw[r][x0];
            hrow[r][X] = fmaf(wx, raw[r][x1] - a, a);
        }
    }
    __syncthreads();

    // Phase C: vertical pass. Two 124-thread halves each cover 27 rows.
    const int half = tid >> 7;         // 0 or 1
    const int lx   = tid & 127;        // x-column within half
    if (lx < XVEC) {
        const int xo    = lx << 2;
        const int ybeg  = half * YHALF;
        const int yend  = ybeg + YHALF;
        float4* orow = (float4*)out + (size_t)plane * OUTH * XVEC
                       + (size_t)(t * YTILE + ybeg) * XVEC + lx;
        int yy = ybeg;
        const int r0 = yi0s[ybeg];
#pragma unroll
        for (int r = 0; r < 5; r++) {
            if (r >= r0 && yy < yend && yi0s[yy] == r) {
                float4 a = *(const float4*)&hrow[r][xo];
                float4 b = *(const float4*)&hrow[r + 1][xo];
                float4 d;
                d.x = b.x - a.x; d.y = b.y - a.y; d.z = b.z - a.z; d.w = b.w - a.w;
                do {
                    float wy = ywy[yy];
                    float4 o;
                    o.x = fmaf(wy, d.x, a.x);
                    o.y = fmaf(wy, d.y, a.y);
                    o.z = fmaf(wy, d.z, a.z);
                    o.w = fmaf(wy, d.w, a.w);
                    __stcs(orow, o);
                    orow += XVEC;
                    yy++;
                } while (yy < yend && yi0s[yy] == r);
            }
        }
    }
}

extern "C" void kernel_launch(void* const* d_in, const int* in_sizes, int n_in,
                              void* d_out, int out_size)
{
    const float* feat = (const float*)d_in[0];
    const float* Wc   = (const float*)d_in[1];
    const float* bc   = (const float*)d_in[2];
    float* out        = (float*)d_out;

    lss_prep_kernel<<<CIN * COUT / 256, 256>>>(Wc);

    dim3 ggrid(PTOT / PB, 2);
    lss_gemm_kernel<<<ggrid, 128>>>(feat, bc);

    dim3 ugrid(NYT, NPLANE);
    lss_upsample_kernel<<<ugrid, 256>>>(out);
}